// round 13
// baseline (speedup 1.0000x reference)
#include <cuda_runtime.h>
#include <cstdint>

// ===========================================================================
// SymbolicEmbeddingBlock — tf32 mma.sync, persistent, 3 CTAs/SM column-split.
//   out[e] = silu( TA'[x[i[e]]] + TB[x[j[e]]] + r[e] @ W3 )   (bias in TA')
//   r[e]   = silu( rbf[e] @ W_rbf + b_rbf )        (phase-1 silu: tanh.approx)
// CTA tile = 128 edges x 64 cols (half = bid&1), 256 thr, 3 CTAs/SM (~80 regs).
// Warp tile M=16 x N=64; A-frags in regs (1-deep pipeline), Bf-half in SMEM.
// acc -> 32KB SMEM (XOR float4 swizzle) -> coalesced 2-rows/warp epilogue.
// ===========================================================================

#define HID    128
#define TILE_E 128

static __device__ float  g_TA[128 * HID];      // bias folded in
static __device__ float  g_TB[128 * HID];
static __device__ float2 g_Bf[16 * 16 * 32];   // [kc][nt][lane] {b0,b1}

// SMEM map (bytes)
#define BF_OFF   0                      // 32768 (this CTA's column half)
#define ACC_OFF  32768                  // 32768 (128 rows x 64 cols f32)
#define WT_OFF   65536                  // 4096
#define TY_OFF   69632                  // tyI[128], tyJ[128] : 1024
#define SMEM_SZ  70656

__device__ __forceinline__ uint32_t f2tf32(float x) {
    uint32_t u;
    asm("cvt.rna.tf32.f32 %0, %1;" : "=r"(u) : "f"(x));
    return u;
}
__device__ __forceinline__ float silu_exact(float x) {
    return __fdividef(x, 1.0f + __expf(-x));
}
__device__ __forceinline__ float silu_tanh(float x) {    // 1 MUFU
    float h = 0.5f * x, t;
    asm("tanh.approx.f32 %0, %1;" : "=f"(t) : "f"(h));
    return fmaf(h, t, h);
}

// ---------------------------------------------------------------------------
// prep (merged): blocks 0-127 -> TA/TB tables; blocks 128-159 -> B fragments.
// ---------------------------------------------------------------------------
__global__ void prep_kernel(const int* __restrict__ code_idx,
                            const float* __restrict__ codebook,
                            const float* __restrict__ W,
                            const float* __restrict__ bias) {
    const int tid = threadIdx.x;
    if (blockIdx.x >= 128) {
        const int idx = (blockIdx.x - 128) * 256 + tid;     // 0..8191
        const int l = idx & 31, nt = (idx >> 5) & 15, kc = idx >> 9;
        const int g = l >> 2, tg = l & 3;
        const int k = kc * 8 + tg, n = nt * 8 + g;
        float2 v;
        v.x = __uint_as_float(f2tf32(W[(256 + k) * HID + n]));
        v.y = __uint_as_float(f2tf32(W[(256 + k + 4) * HID + n]));
        g_Bf[idx] = v;
        return;
    }
    __shared__ float row[HID];
    const int t = blockIdx.x;
    if (tid < HID) {
        int p = tid >> 4, s2 = tid & 15;
        row[tid] = codebook[code_idx[t * 8 + p] * 16 + s2];
    }
    __syncthreads();
    const float* Wb = (tid < HID) ? W : (W + HID * HID);
    const int c = tid & (HID - 1);
    float a0 = 0.f, a1 = 0.f, a2 = 0.f, a3 = 0.f;
#pragma unroll
    for (int d = 0; d < HID; d += 4) {
        a0 = fmaf(row[d],     Wb[(d)     * HID + c], a0);
        a1 = fmaf(row[d + 1], Wb[(d + 1) * HID + c], a1);
        a2 = fmaf(row[d + 2], Wb[(d + 2) * HID + c], a2);
        a3 = fmaf(row[d + 3], Wb[(d + 3) * HID + c], a3);
    }
    const float acc = (a0 + a1) + (a2 + a3);
    if (tid < HID) g_TA[t * HID + c] = acc + bias[c];
    else           g_TB[t * HID + c] = acc;
}

// ---------------------------------------------------------------------------
// edge kernel: persistent, 256 threads, 8 warps, 3 CTAs/SM.
// CTA handles column half (blockIdx.x & 1); warp w owns rows [w*16, w*16+16).
// ---------------------------------------------------------------------------
__global__ __launch_bounds__(256, 3)
void edge_kernel(const int* __restrict__ x, const float* __restrict__ rbf,
                 const int* __restrict__ ei, const int* __restrict__ ej,
                 const float* __restrict__ W_rbf, const float* __restrict__ b_rbf,
                 float* __restrict__ out, int E, int n_et) {
    extern __shared__ char sm[];
    float2* Bf   = (float2*)(sm + BF_OFF);   // [kc16][nt8][lane32]
    float*  accS = (float*)(sm + ACC_OFF);   // [128][64], XOR f4 swizzle
    float4* Wt   = (float4*)(sm + WT_OFF);
    int*    tyI  = (int*)(sm + TY_OFF);
    int*    tyJ  = (int*)(sm + TY_OFF + 512);

    const int tid = threadIdx.x, lane = tid & 31, w = tid >> 5;
    const int g = lane >> 2, tig = lane & 3;
    const int half = blockIdx.x & 1;
    const int cstep = gridDim.x >> 1;

    // ---- one-time staging: Bf half + Wt ----------------------------------
    {
        const float4* gB = (const float4*)g_Bf;
        float4* sB = (float4*)(sm + BF_OFF);
#pragma unroll
        for (int it = 0; it < 8; ++it) {
            const int i = tid + it * 256;           // 0..2047 float4s
            const int kc = i >> 7, nt = (i >> 4) & 7, q = i & 15;
            sB[i] = gB[(kc * 16 + half * 8 + nt) * 16 + q];
        }
        if (tid < HID) {
            const int k = tid;
            float4 a, b;
            a.x = W_rbf[0 * HID + k]; a.y = W_rbf[1 * HID + k];
            a.z = W_rbf[2 * HID + k]; a.w = W_rbf[3 * HID + k];
            b.x = W_rbf[4 * HID + k]; b.y = W_rbf[5 * HID + k];
            b.z = b_rbf[k];           b.w = 0.0f;
            Wt[k * 2 + 0] = a;
            Wt[k * 2 + 1] = b;
        }
    }
    __syncthreads();

    for (int t = blockIdx.x >> 1; t < n_et; t += cstep) {
        const int base = t * TILE_E;
        __syncthreads();      // prev tile's epilogue done (ty/accS reusable)

        // stage node types for this tile
        if (tid < TILE_E) {
            int e = base + tid;
            if (e >= E) e = E - 1;
            tyI[tid] = x[ei[e]];
            tyJ[tid] = x[ej[e]];
        }

        // this thread's 2 edges (rows g, g+8 of warp's 16-row block)
        float rb[2][6];
#pragma unroll
        for (int q = 0; q < 2; ++q) {
            int e = base + w * 16 + g + q * 8;
            if (e >= E) e = E - 1;
            const float2 p0 = *(const float2*)(rbf + e * 6);
            const float2 p1 = *(const float2*)(rbf + e * 6 + 2);
            const float2 p2 = *(const float2*)(rbf + e * 6 + 4);
            rb[q][0] = p0.x; rb[q][1] = p0.y; rb[q][2] = p1.x;
            rb[q][3] = p1.y; rb[q][4] = p2.x; rb[q][5] = p2.y;
        }

        // ---- main loop: pipelined A-compute + mma ------------------------
        float acc[8][4];
#pragma unroll
        for (int nt = 0; nt < 8; ++nt)
#pragma unroll
            for (int q = 0; q < 4; ++q) acc[nt][q] = 0.0f;

        uint32_t Ac[4];

#define COMPUTE_A(KC, D)                                                       \
    {                                                                          \
        const int k0 = (KC) * 8 + tig;                                         \
        const float4 wa = Wt[k0 * 2],       wb = Wt[k0 * 2 + 1];               \
        const float4 va = Wt[(k0 + 4) * 2], vb = Wt[(k0 + 4) * 2 + 1];         \
        float s00 = wb.z, s10 = wb.z, s01 = vb.z, s11 = vb.z;                  \
        s00 = fmaf(rb[0][0], wa.x, s00); s01 = fmaf(rb[0][0], va.x, s01);      \
        s10 = fmaf(rb[1][0], wa.x, s10); s11 = fmaf(rb[1][0], va.x, s11);      \
        s00 = fmaf(rb[0][1], wa.y, s00); s01 = fmaf(rb[0][1], va.y, s01);      \
        s10 = fmaf(rb[1][1], wa.y, s10); s11 = fmaf(rb[1][1], va.y, s11);      \
        s00 = fmaf(rb[0][2], wa.z, s00); s01 = fmaf(rb[0][2], va.z, s01);      \
        s10 = fmaf(rb[1][2], wa.z, s10); s11 = fmaf(rb[1][2], va.z, s11);      \
        s00 = fmaf(rb[0][3], wa.w, s00); s01 = fmaf(rb[0][3], va.w, s01);      \
        s10 = fmaf(rb[1][3], wa.w, s10); s11 = fmaf(rb[1][3], va.w, s11);      \
        s00 = fmaf(rb[0][4], wb.x, s00); s01 = fmaf(rb[0][4], vb.x, s01);      \
        s10 = fmaf(rb[1][4], wb.x, s10); s11 = fmaf(rb[1][4], vb.x, s11);      \
        s00 = fmaf(rb[0][5], wb.y, s00); s01 = fmaf(rb[0][5], vb.y, s01);      \
        s10 = fmaf(rb[1][5], wb.y, s10); s11 = fmaf(rb[1][5], vb.y, s11);      \
        D[0] = f2tf32(silu_tanh(s00));                                         \
        D[1] = f2tf32(silu_tanh(s10));                                         \
        D[2] = f2tf32(silu_tanh(s01));                                         \
        D[3] = f2tf32(silu_tanh(s11));                                         \
    }

        COMPUTE_A(0, Ac);

        const float2* bp = Bf + lane;
#pragma unroll
        for (int kc = 0; kc < 16; ++kc) {
            uint32_t An[4];
            if (kc < 15) COMPUTE_A(kc + 1, An);
#pragma unroll
            for (int nt = 0; nt < 8; ++nt) {
                const float2 b = bp[nt * 32];
                asm("mma.sync.aligned.m16n8k8.row.col.f32.tf32.tf32.f32 "
                    "{%0,%1,%2,%3}, {%4,%5,%6,%7}, {%8,%9}, {%0,%1,%2,%3};\n"
                    : "+f"(acc[nt][0]), "+f"(acc[nt][1]),
                      "+f"(acc[nt][2]), "+f"(acc[nt][3])
                    : "r"(Ac[0]), "r"(Ac[1]), "r"(Ac[2]), "r"(Ac[3]),
                      "r"(__float_as_uint(b.x)), "r"(__float_as_uint(b.y)));
            }
            bp += 256;
            if (kc < 15) {
#pragma unroll
                for (int q = 0; q < 4; ++q) Ac[q] = An[q];
            }
        }
#undef COMPUTE_A

        // ---- dump acc to SMEM (stride 64, XOR-by-row float4 swizzle) -----
#pragma unroll
        for (int hh = 0; hh < 2; ++hh) {
            const int row = w * 16 + g + 8 * hh;
            const int m = (g + 8 * hh);            // row & 15
            float* rp = accS + row * 64;
#pragma unroll
            for (int nt = 0; nt < 8; ++nt) {
                const int c = nt * 8 + 2 * tig;
                const int p = ((c >> 2) ^ m) * 4 + (c & 3);
                *(float2*)(rp + p) =
                    make_float2(acc[nt][2 * hh], acc[nt][2 * hh + 1]);
            }
        }
        __syncthreads();

        // ---- epilogue: 2 rows per warp-iter, coalesced -------------------
#pragma unroll 2
        for (int it = 0; it < 8; ++it) {
            const int el = w * 16 + it * 2 + (lane >> 4);   // 0..127
            const int e = base + el;
            const int jj = lane & 15;
            const int jlog = jj ^ (el & 15);                // logical col4
            const int col = half * 64 + jlog * 4;
            const float4 av = *(const float4*)(accS + el * 64 + jj * 4);
            const float4 ta = *(const float4*)(g_TA + tyI[el] * HID + col);
            const float4 tb = *(const float4*)(g_TB + tyJ[el] * HID + col);
            float4 o;
            o.x = silu_exact(av.x + ta.x + tb.x);
            o.y = silu_exact(av.y + ta.y + tb.y);
            o.z = silu_exact(av.z + ta.z + tb.z);
            o.w = silu_exact(av.w + ta.w + tb.w);
            if (e < E) *(float4*)(out + e * HID + col) = o;
        }
    }
}

// ---------------------------------------------------------------------------
extern "C" void kernel_launch(void* const* d_in, const int* in_sizes, int n_in,
                              void* d_out, int out_size) {
    const int*   x        = (const int*)d_in[0];
    const float* rbf      = (const float*)d_in[1];
    const int*   ei       = (const int*)d_in[2];
    const int*   ej       = (const int*)d_in[3];
    const int*   code_idx = (const int*)d_in[4];
    const float* codebook = (const float*)d_in[5];
    const float* W_rbf    = (const float*)d_in[6];
    const float* b_rbf    = (const float*)d_in[7];
    const float* W        = (const float*)d_in[8];
    const float* bias     = (const float*)d_in[9];
    float*       out      = (float*)d_out;

    const int E = in_sizes[2];
    const int n_et = (E + TILE_E - 1) / TILE_E;

    static bool attr_set = false;
    if (!attr_set) {
        cudaFuncSetAttribute(edge_kernel,
                             cudaFuncAttributeMaxDynamicSharedMemorySize, SMEM_SZ);
        attr_set = true;
    }

    prep_kernel<<<160, 256>>>(code_idx, codebook, W, bias);
    edge_kernel<<<444, 256, SMEM_SZ>>>(x, rbf, ei, ej, W_rbf, b_rbf,
                                       out, E, n_et);
}

// round 14
// speedup vs baseline: 1.1899x; 1.1899x over previous
#include <cuda_runtime.h>
#include <cstdint>

// ===========================================================================
// SymbolicEmbeddingBlock — bf16 mma.sync m16n8k16, persistent, 2 CTAs/SM.
//   out[e] = silu( TA'[x[i[e]]] + TB[x[j[e]]] + r[e] @ W3 )   (bias in TA')
//   r[e]   = silu( rbf[e] @ W_rbf + b_rbf )        (phase-1 silu: tanh.approx)
// Grid = 296 persistent CTAs, 256 thr. Warp tile M=16 x N=128.
// B (W3) pre-packed bf16x2 fragments (32KB, staged once). A-frags computed
// in registers (1-deep pipeline) and packed via cvt.rn.bf16x2.
// acc -> 32KB SMEM (two 64-row halves) -> coalesced fp32 epilogue.
// ===========================================================================

#define HID    128
#define TILE_E 128

static __device__ float g_TA[128 * HID];       // bias folded in
static __device__ float g_TB[128 * HID];
static __device__ uint2 g_Bf[8 * 16 * 32];     // [kc8][nt16][lane] {b0,b1} bf16x2

// SMEM map (bytes) — no aliasing.
#define BF_OFF   0                      // 32768
#define ACC_OFF  32768                  // 32768 (64 rows x 128 cols f32)
#define WT_OFF   65536                  // 4096
#define TY_OFF   69632                  // tyI[128], tyJ[128] : 1024
#define SMEM_SZ  70656

__device__ __forceinline__ uint32_t pack_bf2(float lo, float hi) {
    uint32_t r;            // d.hi = first operand, d.lo = second operand
    asm("cvt.rn.bf16x2.f32 %0, %1, %2;" : "=r"(r) : "f"(hi), "f"(lo));
    return r;
}
__device__ __forceinline__ float silu_exact(float x) {
    return __fdividef(x, 1.0f + __expf(-x));
}
__device__ __forceinline__ float silu_tanh(float x) {    // 1 MUFU
    float h = 0.5f * x, t;
    asm("tanh.approx.f32 %0, %1;" : "=f"(t) : "f"(h));
    return fmaf(h, t, h);
}

// ---------------------------------------------------------------------------
// prep: blocks 0-127 -> TA/TB tables; blocks 128-143 -> bf16 B fragments.
// ---------------------------------------------------------------------------
__global__ void prep_kernel(const int* __restrict__ code_idx,
                            const float* __restrict__ codebook,
                            const float* __restrict__ W,
                            const float* __restrict__ bias) {
    const int tid = threadIdx.x;
    if (blockIdx.x >= 128) {
        const int idx = (blockIdx.x - 128) * 256 + tid;     // 0..4095
        const int l = idx & 31, nt = (idx >> 5) & 15, kc = idx >> 9;
        const int g = l >> 2, tg = l & 3;
        const int n = nt * 8 + g;
        const int k0 = kc * 16 + 2 * tg;
        const float* W3 = W + 256 * HID;
        uint2 v;
        v.x = pack_bf2(W3[(k0)     * HID + n], W3[(k0 + 1) * HID + n]);
        v.y = pack_bf2(W3[(k0 + 8) * HID + n], W3[(k0 + 9) * HID + n]);
        g_Bf[idx] = v;
        return;
    }
    __shared__ float row[HID];
    const int t = blockIdx.x;
    if (tid < HID) {
        int p = tid >> 4, s2 = tid & 15;
        row[tid] = codebook[code_idx[t * 8 + p] * 16 + s2];
    }
    __syncthreads();
    const float* Wb = (tid < HID) ? W : (W + HID * HID);
    const int c = tid & (HID - 1);
    float a0 = 0.f, a1 = 0.f, a2 = 0.f, a3 = 0.f;
#pragma unroll
    for (int d = 0; d < HID; d += 4) {
        a0 = fmaf(row[d],     Wb[(d)     * HID + c], a0);
        a1 = fmaf(row[d + 1], Wb[(d + 1) * HID + c], a1);
        a2 = fmaf(row[d + 2], Wb[(d + 2) * HID + c], a2);
        a3 = fmaf(row[d + 3], Wb[(d + 3) * HID + c], a3);
    }
    const float acc = (a0 + a1) + (a2 + a3);
    if (tid < HID) g_TA[t * HID + c] = acc + bias[c];
    else           g_TB[t * HID + c] = acc;
}

// ---------------------------------------------------------------------------
// edge kernel: persistent, 256 threads, 8 warps, 2 CTAs/SM.
// Warp w owns edge rows [w*16, w*16+16); full 128-col width.
// ---------------------------------------------------------------------------
__global__ __launch_bounds__(256, 2)
void edge_kernel(const int* __restrict__ x, const float* __restrict__ rbf,
                 const int* __restrict__ ei, const int* __restrict__ ej,
                 const float* __restrict__ W_rbf, const float* __restrict__ b_rbf,
                 float* __restrict__ out, int E, int n_tiles) {
    extern __shared__ char sm[];
    uint2*  Bf   = (uint2*)(sm + BF_OFF);    // [kc8][nt16][lane32]
    float*  accS = (float*)(sm + ACC_OFF);
    float4* Wt   = (float4*)(sm + WT_OFF);
    int*    tyI  = (int*)(sm + TY_OFF);
    int*    tyJ  = (int*)(sm + TY_OFF + 512);

    const int tid = threadIdx.x, lane = tid & 31, w = tid >> 5;
    const int g = lane >> 2, tig = lane & 3;

    // ---- one-time staging: Bf + Wt ---------------------------------------
    {
        const float4* gB = (const float4*)g_Bf;
        float4* sB = (float4*)(sm + BF_OFF);
#pragma unroll
        for (int i = 0; i < 8; ++i) sB[tid + i * 256] = gB[tid + i * 256];
        if (tid < HID) {
            const int k = tid;
            float4 a, b;
            a.x = W_rbf[0 * HID + k]; a.y = W_rbf[1 * HID + k];
            a.z = W_rbf[2 * HID + k]; a.w = W_rbf[3 * HID + k];
            b.x = W_rbf[4 * HID + k]; b.y = W_rbf[5 * HID + k];
            b.z = b_rbf[k];           b.w = 0.0f;
            Wt[k * 2 + 0] = a;
            Wt[k * 2 + 1] = b;
        }
    }
    __syncthreads();

    for (int t = blockIdx.x; t < n_tiles; t += gridDim.x) {
        const int base = t * TILE_E;

        // stage node types for this tile
        if (tid < TILE_E) {
            int e = base + tid;
            if (e >= E) e = E - 1;
            tyI[tid] = x[ei[e]];
            tyJ[tid] = x[ej[e]];
        }

        // this thread's 2 edges (rows g, g+8 of warp's 16-row block)
        float rb[2][6];
#pragma unroll
        for (int q = 0; q < 2; ++q) {
            int e = base + w * 16 + g + q * 8;
            if (e >= E) e = E - 1;
            const float2 p0 = *(const float2*)(rbf + e * 6);
            const float2 p1 = *(const float2*)(rbf + e * 6 + 2);
            const float2 p2 = *(const float2*)(rbf + e * 6 + 4);
            rb[q][0] = p0.x; rb[q][1] = p0.y; rb[q][2] = p1.x;
            rb[q][3] = p1.y; rb[q][4] = p2.x; rb[q][5] = p2.y;
        }

        // ---- main loop: pipelined A-compute + bf16 mma -------------------
        float acc[16][4];
#pragma unroll
        for (int nt = 0; nt < 16; ++nt)
#pragma unroll
            for (int q = 0; q < 4; ++q) acc[nt][q] = 0.0f;

        uint32_t Ac[4];

        // A-fragment for one k16 chunk:
        //   z(row, k) for rows {g, g+8}, k in {k0, k0+1, k0+8, k0+9},
        //   k0 = kc*16 + 2*tig.  Packed bf16x2 per mma m16n8k16 layout.
#define COMPUTE_A(KC, D)                                                       \
    {                                                                          \
        const int k0 = (KC) * 16 + 2 * tig;                                    \
        const float4 wa0 = Wt[(k0)     * 2], wb0 = Wt[(k0)     * 2 + 1];       \
        const float4 wa1 = Wt[(k0 + 1) * 2], wb1 = Wt[(k0 + 1) * 2 + 1];       \
        const float4 wa8 = Wt[(k0 + 8) * 2], wb8 = Wt[(k0 + 8) * 2 + 1];       \
        const float4 wa9 = Wt[(k0 + 9) * 2], wb9 = Wt[(k0 + 9) * 2 + 1];       \
        float z00 = wb0.z, z10 = wb0.z, z01 = wb1.z, z11 = wb1.z;              \
        float z08 = wb8.z, z18 = wb8.z, z09 = wb9.z, z19 = wb9.z;              \
        z00 = fmaf(rb[0][0], wa0.x, z00); z10 = fmaf(rb[1][0], wa0.x, z10);    \
        z01 = fmaf(rb[0][0], wa1.x, z01); z11 = fmaf(rb[1][0], wa1.x, z11);    \
        z08 = fmaf(rb[0][0], wa8.x, z08); z18 = fmaf(rb[1][0], wa8.x, z18);    \
        z09 = fmaf(rb[0][0], wa9.x, z09); z19 = fmaf(rb[1][0], wa9.x, z19);    \
        z00 = fmaf(rb[0][1], wa0.y, z00); z10 = fmaf(rb[1][1], wa0.y, z10);    \
        z01 = fmaf(rb[0][1], wa1.y, z01); z11 = fmaf(rb[1][1], wa1.y, z11);    \
        z08 = fmaf(rb[0][1], wa8.y, z08); z18 = fmaf(rb[1][1], wa8.y, z18);    \
        z09 = fmaf(rb[0][1], wa9.y, z09); z19 = fmaf(rb[1][1], wa9.y, z19);    \
        z00 = fmaf(rb[0][2], wa0.z, z00); z10 = fmaf(rb[1][2], wa0.z, z10);    \
        z01 = fmaf(rb[0][2], wa1.z, z01); z11 = fmaf(rb[1][2], wa1.z, z11);    \
        z08 = fmaf(rb[0][2], wa8.z, z08); z18 = fmaf(rb[1][2], wa8.z, z18);    \
        z09 = fmaf(rb[0][2], wa9.z, z09); z19 = fmaf(rb[1][2], wa9.z, z19);    \
        z00 = fmaf(rb[0][3], wa0.w, z00); z10 = fmaf(rb[1][3], wa0.w, z10);    \
        z01 = fmaf(rb[0][3], wa1.w, z01); z11 = fmaf(rb[1][3], wa1.w, z11);    \
        z08 = fmaf(rb[0][3], wa8.w, z08); z18 = fmaf(rb[1][3], wa8.w, z18);    \
        z09 = fmaf(rb[0][3], wa9.w, z09); z19 = fmaf(rb[1][3], wa9.w, z19);    \
        z00 = fmaf(rb[0][4], wb0.x, z00); z10 = fmaf(rb[1][4], wb0.x, z10);    \
        z01 = fmaf(rb[0][4], wb1.x, z01); z11 = fmaf(rb[1][4], wb1.x, z11);    \
        z08 = fmaf(rb[0][4], wb8.x, z08); z18 = fmaf(rb[1][4], wb8.x, z18);    \
        z09 = fmaf(rb[0][4], wb9.x, z09); z19 = fmaf(rb[1][4], wb9.x, z19);    \
        z00 = fmaf(rb[0][5], wb0.y, z00); z10 = fmaf(rb[1][5], wb0.y, z10);    \
        z01 = fmaf(rb[0][5], wb1.y, z01); z11 = fmaf(rb[1][5], wb1.y, z11);    \
        z08 = fmaf(rb[0][5], wb8.y, z08); z18 = fmaf(rb[1][5], wb8.y, z18);    \
        z09 = fmaf(rb[0][5], wb9.y, z09); z19 = fmaf(rb[1][5], wb9.y, z19);    \
        D[0] = pack_bf2(silu_tanh(z00), silu_tanh(z01));  /* row g,   k0..k0+1 */ \
        D[1] = pack_bf2(silu_tanh(z10), silu_tanh(z11));  /* row g+8           */ \
        D[2] = pack_bf2(silu_tanh(z08), silu_tanh(z09));  /* row g,   +8..+9   */ \
        D[3] = pack_bf2(silu_tanh(z18), silu_tanh(z19));  /* row g+8           */ \
    }

        COMPUTE_A(0, Ac);

        const uint2* bp = Bf + lane;
#pragma unroll
        for (int kc = 0; kc < 8; ++kc) {
            uint32_t An[4];
            if (kc < 7) COMPUTE_A(kc + 1, An);
#pragma unroll
            for (int nt = 0; nt < 16; ++nt) {
                const uint2 b = bp[nt * 32];
                asm("mma.sync.aligned.m16n8k16.row.col.f32.bf16.bf16.f32 "
                    "{%0,%1,%2,%3}, {%4,%5,%6,%7}, {%8,%9}, {%0,%1,%2,%3};\n"
                    : "+f"(acc[nt][0]), "+f"(acc[nt][1]),
                      "+f"(acc[nt][2]), "+f"(acc[nt][3])
                    : "r"(Ac[0]), "r"(Ac[1]), "r"(Ac[2]), "r"(Ac[3]),
                      "r"(b.x), "r"(b.y));
            }
            bp += 512;
            if (kc < 7) {
#pragma unroll
                for (int q = 0; q < 4; ++q) Ac[q] = An[q];
            }
        }
#undef COMPUTE_A

        // ---- two-half dump + epilogue ------------------------------------
#pragma unroll
        for (int h = 0; h < 2; ++h) {
            __syncthreads();   // previous half fully consumed
            if ((w >> 2) == h) {
                const int rw = (w & 3) * 16;     // local row base in half
                const int xr = g << 2;
#pragma unroll
                for (int hh = 0; hh < 2; ++hh) {
                    float* rp = accS + (rw + g + 8 * hh) * HID;
#pragma unroll
                    for (int nt = 0; nt < 16; ++nt) {
                        const int col = (nt * 8 + 2 * tig) ^ xr;
                        *(float2*)(rp + col) =
                            make_float2(acc[nt][2 * hh], acc[nt][2 * hh + 1]);
                    }
                }
            }
            __syncthreads();
#pragma unroll 2
            for (int it = 0; it < 8; ++it) {
                const int ell = w * 8 + it;            // 0..63 in half
                const int el = h * 64 + ell;           // 0..127 in tile
                const int e = base + el;
                const int xc = (lane * 4) ^ ((ell & 7) << 2);
                const float4 av = *(const float4*)(accS + ell * HID + xc);
                const float4 ta = *(const float4*)(g_TA + tyI[el] * HID + lane * 4);
                const float4 tb = *(const float4*)(g_TB + tyJ[el] * HID + lane * 4);
                float4 o;
                o.x = silu_exact(av.x + ta.x + tb.x);
                o.y = silu_exact(av.y + ta.y + tb.y);
                o.z = silu_exact(av.z + ta.z + tb.z);
                o.w = silu_exact(av.w + ta.w + tb.w);
                if (e < E) *(float4*)(out + e * HID + lane * 4) = o;
            }
        }
        __syncthreads();   // ty/accS safe to rewrite next iteration
    }
}

// ---------------------------------------------------------------------------
extern "C" void kernel_launch(void* const* d_in, const int* in_sizes, int n_in,
                              void* d_out, int out_size) {
    const int*   x        = (const int*)d_in[0];
    const float* rbf      = (const float*)d_in[1];
    const int*   ei       = (const int*)d_in[2];
    const int*   ej       = (const int*)d_in[3];
    const int*   code_idx = (const int*)d_in[4];
    const float* codebook = (const float*)d_in[5];
    const float* W_rbf    = (const float*)d_in[6];
    const float* b_rbf    = (const float*)d_in[7];
    const float* W        = (const float*)d_in[8];
    const float* bias     = (const float*)d_in[9];
    float*       out      = (float*)d_out;

    const int E = in_sizes[2];
    const int n_tiles = (E + TILE_E - 1) / TILE_E;

    static bool attr_set = false;
    if (!attr_set) {
        cudaFuncSetAttribute(edge_kernel,
                             cudaFuncAttributeMaxDynamicSharedMemorySize, SMEM_SZ);
        attr_set = true;
    }

    prep_kernel<<<144, 256>>>(code_idx, codebook, W, bias);
    edge_kernel<<<296, 256, SMEM_SZ>>>(x, rbf, ei, ej, W_rbf, b_rbf,
                                       out, E, n_tiles);
}

// round 17
// speedup vs baseline: 1.2637x; 1.0620x over previous
#include <cuda_runtime.h>
#include <cstdint>

// ===========================================================================
// SymbolicEmbeddingBlock — fp16 mma.sync m16n8k16, persistent, 2 CTAs/SM.
//   out[e] = silu( TA'[x[i[e]]] + TB[x[j[e]]] + r[e] @ W3 )   (bias in TA')
//   r[e]   = silu( rbf[e] @ W_rbf + b_rbf )        (phase-1 silu: tanh.approx)
// fp16 (11-bit mantissa = tf32-grade accuracy) with k16 -> half B-LDS, half mma.
// 2 barriers/tile: mainloop -> bar -> full dump -> bar -> {prefetch t+1;
// epilogue} ... next mainloop (no barrier: epilogue overlaps next tile).
// (Identical to R15 submission — that round died to a broker infra failure
//  before compile/run; re-benching unchanged per rigor.md.)
// ===========================================================================

#define HID    128
#define TILE_E 128

static __device__ float g_TA[128 * HID];       // bias folded in
static __device__ float g_TB[128 * HID];
static __device__ uint2 g_Bf[8 * 16 * 32];     // [kc8][nt16][lane] {b0,b1} f16x2

// SMEM map (bytes) — no aliasing.
#define BF_OFF   0                      // 32768
#define ACC_OFF  32768                  // 65536 (128 rows x 128 cols f32)
#define WT_OFF   98304                  // 4096
#define TY_OFF   102400                 // tyI[2][128], tyJ[2][128] : 2048
#define SMEM_SZ  104448

__device__ __forceinline__ uint32_t pack_f16x2(float lo, float hi) {
    uint32_t r;            // %1 -> d.hi, %2 -> d.lo
    asm("cvt.rn.f16x2.f32 %0, %1, %2;" : "=r"(r) : "f"(hi), "f"(lo));
    return r;
}
__device__ __forceinline__ float silu_exact(float x) {
    return __fdividef(x, 1.0f + __expf(-x));
}
__device__ __forceinline__ float silu_tanh(float x) {    // 1 MUFU
    float h = 0.5f * x, t;
    asm("tanh.approx.f32 %0, %1;" : "=f"(t) : "f"(h));
    return fmaf(h, t, h);
}

// ---------------------------------------------------------------------------
// prep: blocks 0-127 -> TA/TB tables; blocks 128-143 -> fp16 B fragments.
// ---------------------------------------------------------------------------
__global__ void prep_kernel(const int* __restrict__ code_idx,
                            const float* __restrict__ codebook,
                            const float* __restrict__ W,
                            const float* __restrict__ bias) {
    const int tid = threadIdx.x;
    if (blockIdx.x >= 128) {
        const int idx = (blockIdx.x - 128) * 256 + tid;     // 0..4095
        const int l = idx & 31, nt = (idx >> 5) & 15, kc = idx >> 9;
        const int g = l >> 2, tg = l & 3;
        const int n = nt * 8 + g;
        const int k0 = kc * 16 + 2 * tg;
        const float* W3 = W + 256 * HID;
        uint2 v;
        v.x = pack_f16x2(W3[(k0)     * HID + n], W3[(k0 + 1) * HID + n]);
        v.y = pack_f16x2(W3[(k0 + 8) * HID + n], W3[(k0 + 9) * HID + n]);
        g_Bf[idx] = v;
        return;
    }
    __shared__ float row[HID];
    const int t = blockIdx.x;
    if (tid < HID) {
        int p = tid >> 4, s2 = tid & 15;
        row[tid] = codebook[code_idx[t * 8 + p] * 16 + s2];
    }
    __syncthreads();
    const float* Wb = (tid < HID) ? W : (W + HID * HID);
    const int c = tid & (HID - 1);
    float a0 = 0.f, a1 = 0.f, a2 = 0.f, a3 = 0.f;
#pragma unroll
    for (int d = 0; d < HID; d += 4) {
        a0 = fmaf(row[d],     Wb[(d)     * HID + c], a0);
        a1 = fmaf(row[d + 1], Wb[(d + 1) * HID + c], a1);
        a2 = fmaf(row[d + 2], Wb[(d + 2) * HID + c], a2);
        a3 = fmaf(row[d + 3], Wb[(d + 3) * HID + c], a3);
    }
    const float acc = (a0 + a1) + (a2 + a3);
    if (tid < HID) g_TA[t * HID + c] = acc + bias[c];
    else           g_TB[t * HID + c] = acc;
}

// ---------------------------------------------------------------------------
// edge kernel: persistent, 256 threads, 8 warps, 2 CTAs/SM.
// Warp w owns edge rows [w*16, w*16+16); full 128-col width.
// ---------------------------------------------------------------------------
__global__ __launch_bounds__(256, 2)
void edge_kernel(const int* __restrict__ x, const float* __restrict__ rbf,
                 const int* __restrict__ ei, const int* __restrict__ ej,
                 const float* __restrict__ W_rbf, const float* __restrict__ b_rbf,
                 float* __restrict__ out, int E, int n_tiles) {
    extern __shared__ char sm[];
    uint2*  Bf   = (uint2*)(sm + BF_OFF);    // [kc8][nt16][lane32]
    float*  accS = (float*)(sm + ACC_OFF);   // [128][128]
    float4* Wt   = (float4*)(sm + WT_OFF);
    int*    tyI  = (int*)(sm + TY_OFF);          // [2][128]
    int*    tyJ  = (int*)(sm + TY_OFF + 1024);   // [2][128]

    const int tid = threadIdx.x, lane = tid & 31, w = tid >> 5;
    const int g = lane >> 2, tig = lane & 3;
    const int G = gridDim.x;

    // ---- one-time staging: Bf + Wt ---------------------------------------
    {
        const float4* gB = (const float4*)g_Bf;
        float4* sB = (float4*)(sm + BF_OFF);
#pragma unroll
        for (int i = 0; i < 8; ++i) sB[tid + i * 256] = gB[tid + i * 256];
        if (tid < HID) {
            const int k = tid;
            float4 a, b;
            a.x = W_rbf[0 * HID + k]; a.y = W_rbf[1 * HID + k];
            a.z = W_rbf[2 * HID + k]; a.w = W_rbf[3 * HID + k];
            b.x = W_rbf[4 * HID + k]; b.y = W_rbf[5 * HID + k];
            b.z = b_rbf[k];           b.w = 0.0f;
            Wt[k * 2 + 0] = a;
            Wt[k * 2 + 1] = b;
        }
    }

    int t = blockIdx.x;
    int pb = 0;

    // ---- pre-stage tile t0: node types + rbf -----------------------------
    float rb[2][6];
    if (t < n_tiles) {
        if (tid < TILE_E) {
            int e = t * TILE_E + tid;
            if (e >= E) e = E - 1;
            tyI[tid] = x[ei[e]];
            tyJ[tid] = x[ej[e]];
        }
#pragma unroll
        for (int q = 0; q < 2; ++q) {
            int e = t * TILE_E + w * 16 + g + q * 8;
            if (e >= E) e = E - 1;
            const float2 p0 = *(const float2*)(rbf + e * 6);
            const float2 p1 = *(const float2*)(rbf + e * 6 + 2);
            const float2 p2 = *(const float2*)(rbf + e * 6 + 4);
            rb[q][0] = p0.x; rb[q][1] = p0.y; rb[q][2] = p1.x;
            rb[q][3] = p1.y; rb[q][4] = p2.x; rb[q][5] = p2.y;
        }
    }
    __syncthreads();

    for (; t < n_tiles; t += G) {
        const int base = t * TILE_E;

        // ---- mainloop: pipelined A-compute + fp16 mma --------------------
        float acc[16][4];
#pragma unroll
        for (int nt = 0; nt < 16; ++nt)
#pragma unroll
            for (int q = 0; q < 4; ++q) acc[nt][q] = 0.0f;

        uint32_t Ac[4];

#define COMPUTE_A(KC, D)                                                       \
    {                                                                          \
        const int k0 = (KC) * 16 + 2 * tig;                                    \
        const float4 wa0 = Wt[(k0)     * 2], wb0 = Wt[(k0)     * 2 + 1];       \
        const float4 wa1 = Wt[(k0 + 1) * 2], wb1 = Wt[(k0 + 1) * 2 + 1];       \
        const float4 wa8 = Wt[(k0 + 8) * 2], wb8 = Wt[(k0 + 8) * 2 + 1];       \
        const float4 wa9 = Wt[(k0 + 9) * 2], wb9 = Wt[(k0 + 9) * 2 + 1];       \
        float z00 = wb0.z, z10 = wb0.z, z01 = wb1.z, z11 = wb1.z;              \
        float z08 = wb8.z, z18 = wb8.z, z09 = wb9.z, z19 = wb9.z;              \
        z00 = fmaf(rb[0][0], wa0.x, z00); z10 = fmaf(rb[1][0], wa0.x, z10);    \
        z01 = fmaf(rb[0][0], wa1.x, z01); z11 = fmaf(rb[1][0], wa1.x, z11);    \
        z08 = fmaf(rb[0][0], wa8.x, z08); z18 = fmaf(rb[1][0], wa8.x, z18);    \
        z09 = fmaf(rb[0][0], wa9.x, z09); z19 = fmaf(rb[1][0], wa9.x, z19);    \
        z00 = fmaf(rb[0][1], wa0.y, z00); z10 = fmaf(rb[1][1], wa0.y, z10);    \
        z01 = fmaf(rb[0][1], wa1.y, z01); z11 = fmaf(rb[1][1], wa1.y, z11);    \
        z08 = fmaf(rb[0][1], wa8.y, z08); z18 = fmaf(rb[1][1], wa8.y, z18);    \
        z09 = fmaf(rb[0][1], wa9.y, z09); z19 = fmaf(rb[1][1], wa9.y, z19);    \
        z00 = fmaf(rb[0][2], wa0.z, z00); z10 = fmaf(rb[1][2], wa0.z, z10);    \
        z01 = fmaf(rb[0][2], wa1.z, z01); z11 = fmaf(rb[1][2], wa1.z, z11);    \
        z08 = fmaf(rb[0][2], wa8.z, z08); z18 = fmaf(rb[1][2], wa8.z, z18);    \
        z09 = fmaf(rb[0][2], wa9.z, z09); z19 = fmaf(rb[1][2], wa9.z, z19);    \
        z00 = fmaf(rb[0][3], wa0.w, z00); z10 = fmaf(rb[1][3], wa0.w, z10);    \
        z01 = fmaf(rb[0][3], wa1.w, z01); z11 = fmaf(rb[1][3], wa1.w, z11);    \
        z08 = fmaf(rb[0][3], wa8.w, z08); z18 = fmaf(rb[1][3], wa8.w, z18);    \
        z09 = fmaf(rb[0][3], wa9.w, z09); z19 = fmaf(rb[1][3], wa9.w, z19);    \
        z00 = fmaf(rb[0][4], wb0.x, z00); z10 = fmaf(rb[1][4], wb0.x, z10);    \
        z01 = fmaf(rb[0][4], wb1.x, z01); z11 = fmaf(rb[1][4], wb1.x, z11);    \
        z08 = fmaf(rb[0][4], wb8.x, z08); z18 = fmaf(rb[1][4], wb8.x, z18);    \
        z09 = fmaf(rb[0][4], wb9.x, z09); z19 = fmaf(rb[1][4], wb9.x, z19);    \
        z00 = fmaf(rb[0][5], wb0.y, z00); z10 = fmaf(rb[1][5], wb0.y, z10);    \
        z01 = fmaf(rb[0][5], wb1.y, z01); z11 = fmaf(rb[1][5], wb1.y, z11);    \
        z08 = fmaf(rb[0][5], wb8.y, z08); z18 = fmaf(rb[1][5], wb8.y, z18);    \
        z09 = fmaf(rb[0][5], wb9.y, z09); z19 = fmaf(rb[1][5], wb9.y, z19);    \
        D[0] = pack_f16x2(silu_tanh(z00), silu_tanh(z01));                     \
        D[1] = pack_f16x2(silu_tanh(z10), silu_tanh(z11));                     \
        D[2] = pack_f16x2(silu_tanh(z08), silu_tanh(z09));                     \
        D[3] = pack_f16x2(silu_tanh(z18), silu_tanh(z19));                     \
    }

        COMPUTE_A(0, Ac);

        const uint2* bp = Bf + lane;
#pragma unroll
        for (int kc = 0; kc < 8; ++kc) {
            uint32_t An[4];
            if (kc < 7) COMPUTE_A(kc + 1, An);
#pragma unroll
            for (int nt = 0; nt < 16; ++nt) {
                const uint2 b = bp[nt * 32];
                asm("mma.sync.aligned.m16n8k16.row.col.f32.f16.f16.f32 "
                    "{%0,%1,%2,%3}, {%4,%5,%6,%7}, {%8,%9}, {%0,%1,%2,%3};\n"
                    : "+f"(acc[nt][0]), "+f"(acc[nt][1]),
                      "+f"(acc[nt][2]), "+f"(acc[nt][3])
                    : "r"(Ac[0]), "r"(Ac[1]), "r"(Ac[2]), "r"(Ac[3]),
                      "r"(b.x), "r"(b.y));
            }
            bp += 512;
            if (kc < 7) {
#pragma unroll
                for (int q = 0; q < 4; ++q) Ac[q] = An[q];
            }
        }
#undef COMPUTE_A

        __syncthreads();   // accS free (epilogue of previous tile finished)

        // ---- full dump: this warp's 16 rows (XOR col swizzle) ------------
#pragma unroll
        for (int hh = 0; hh < 2; ++hh) {
            const int xr = g << 2;
            float* rp = accS + (w * 16 + g + 8 * hh) * HID;
#pragma unroll
            for (int nt = 0; nt < 16; ++nt) {
                const int col = (nt * 8 + 2 * tig) ^ xr;
                *(float2*)(rp + col) =
                    make_float2(acc[nt][2 * hh], acc[nt][2 * hh + 1]);
            }
        }
        __syncthreads();   // accS fully written

        // ---- prefetch next tile (rb + node types) ------------------------
        const int tn = t + G;
        if (tn < n_tiles) {
            if (tid < TILE_E) {
                int e = tn * TILE_E + tid;
                if (e >= E) e = E - 1;
                tyI[(pb ^ 1) * TILE_E + tid] = x[ei[e]];
                tyJ[(pb ^ 1) * TILE_E + tid] = x[ej[e]];
            }
#pragma unroll
            for (int q = 0; q < 2; ++q) {
                int e = tn * TILE_E + w * 16 + g + q * 8;
                if (e >= E) e = E - 1;
                const float2 p0 = *(const float2*)(rbf + e * 6);
                const float2 p1 = *(const float2*)(rbf + e * 6 + 2);
                const float2 p2 = *(const float2*)(rbf + e * 6 + 4);
                rb[q][0] = p0.x; rb[q][1] = p0.y; rb[q][2] = p1.x;
                rb[q][3] = p1.y; rb[q][4] = p2.x; rb[q][5] = p2.y;
            }
        }

        // ---- epilogue: 16 rows per warp, coalesced (overlaps next tile) --
        const int* tI = tyI + pb * TILE_E;
        const int* tJ = tyJ + pb * TILE_E;
#pragma unroll 2
        for (int it = 0; it < 16; ++it) {
            const int el = w * 16 + it;                 // 0..127
            const int e = base + el;
            const int xc = (lane * 4) ^ ((el & 7) << 2);
            const float4 av = *(const float4*)(accS + el * HID + xc);
            const float4 ta = *(const float4*)(g_TA + tI[el] * HID + lane * 4);
            const float4 tb = *(const float4*)(g_TB + tJ[el] * HID + lane * 4);
            float4 o;
            o.x = silu_exact(av.x + ta.x + tb.x);
            o.y = silu_exact(av.y + ta.y + tb.y);
            o.z = silu_exact(av.z + ta.z + tb.z);
            o.w = silu_exact(av.w + ta.w + tb.w);
            if (e < E) *(float4*)(out + e * HID + lane * 4) = o;
        }
        pb ^= 1;
        // NOTE: no barrier here — fast warps begin next tile's mainloop
        // while slow warps finish the epilogue.
    }
}

// ---------------------------------------------------------------------------
extern "C" void kernel_launch(void* const* d_in, const int* in_sizes, int n_in,
                              void* d_out, int out_size) {
    const int*   x        = (const int*)d_in[0];
    const float* rbf      = (const float*)d_in[1];
    const int*   ei       = (const int*)d_in[2];
    const int*   ej       = (const int*)d_in[3];
    const int*   code_idx = (const int*)d_in[4];
    const float* codebook = (const float*)d_in[5];
    const float* W_rbf    = (const float*)d_in[6];
    const float* b_rbf    = (const float*)d_in[7];
    const float* W        = (const float*)d_in[8];
    const float* bias     = (const float*)d_in[9];
    float*       out      = (float*)d_out;

    const int E = in_sizes[2];
    const int n_tiles = (E + TILE_E - 1) / TILE_E;

    static bool attr_set = false;
    if (!attr_set) {
        cudaFuncSetAttribute(edge_kernel,
                             cudaFuncAttributeMaxDynamicSharedMemorySize, SMEM_SZ);
        attr_set = true;
    }

    prep_kernel<<<144, 256>>>(code_idx, codebook, W, bias);
    edge_kernel<<<296, 256, SMEM_SZ>>>(x, rbf, ei, ej, W_rbf, b_rbf,
                                       out, E, n_tiles);
}